// round 1
// baseline (speedup 1.0000x reference)
#include <cuda_runtime.h>
#include <cuda_fp16.h>
#include <cstdint>

#define NB 2
#define NH 16
#define HD 64
#define SEQ 2048
#define HID 1024

// fp16 scratch: Q/K/V in [b, h, s, d] layout (8 MB each, static => allocation-free)
__device__ __half g_q[(size_t)NB * NH * SEQ * HD];
__device__ __half g_k[(size_t)NB * NH * SEQ * HD];
__device__ __half g_v[(size_t)NB * NH * SEQ * HD];

// ---------------------------------------------------------------------------
// PTX helpers
// ---------------------------------------------------------------------------
__device__ __forceinline__ uint32_t smem_u32(const void* p) {
    return (uint32_t)__cvta_generic_to_shared(p);
}

__device__ __forceinline__ void ldmatrix_x4(uint32_t& r0, uint32_t& r1, uint32_t& r2,
                                            uint32_t& r3, uint32_t addr) {
    asm volatile("ldmatrix.sync.aligned.m8n8.x4.shared.b16 {%0,%1,%2,%3},[%4];\n"
                 : "=r"(r0), "=r"(r1), "=r"(r2), "=r"(r3) : "r"(addr));
}

__device__ __forceinline__ void ldmatrix_x4_trans(uint32_t& r0, uint32_t& r1, uint32_t& r2,
                                                  uint32_t& r3, uint32_t addr) {
    asm volatile("ldmatrix.sync.aligned.m8n8.x4.trans.shared.b16 {%0,%1,%2,%3},[%4];\n"
                 : "=r"(r0), "=r"(r1), "=r"(r2), "=r"(r3) : "r"(addr));
}

__device__ __forceinline__ void mma16816(float* c, const uint32_t* a, const uint32_t* b) {
    asm volatile(
        "mma.sync.aligned.m16n8k16.row.col.f32.f16.f16.f32 "
        "{%0,%1,%2,%3},{%4,%5,%6,%7},{%8,%9},{%0,%1,%2,%3};\n"
        : "+f"(c[0]), "+f"(c[1]), "+f"(c[2]), "+f"(c[3])
        : "r"(a[0]), "r"(a[1]), "r"(a[2]), "r"(a[3]), "r"(b[0]), "r"(b[1]));
}

__device__ __forceinline__ uint32_t pack_half2(float x, float y) {
    __half2 h = __floats2half2_rn(x, y);
    return *(uint32_t*)&h;
}

// ---------------------------------------------------------------------------
// QKV projection GEMM: Y = X @ W + b, output fp16 in [b,h,s,d] scratch.
// M=4096, N=1024, K=1024. CTA tile 128x128x32, 8 warps (2x4), warp tile 64x32.
// gridDim.z selects Q / K / V.
// ---------------------------------------------------------------------------
__global__ __launch_bounds__(256) void qkv_gemm(
    const float* __restrict__ former, const float* __restrict__ latter,
    const float* __restrict__ Wq, const float* __restrict__ bq,
    const float* __restrict__ Wk, const float* __restrict__ bk,
    const float* __restrict__ Wv, const float* __restrict__ bv) {
    const int which = blockIdx.z;
    const float* X    = (which == 0) ? former : latter;
    const float* W    = (which == 0) ? Wq : (which == 1) ? Wk : Wv;
    const float* bias = (which == 0) ? bq : (which == 1) ? bk : bv;
    __half* out       = (which == 0) ? g_q : (which == 1) ? g_k : g_v;

    __shared__ __align__(16) __half sA[128 * 40];   // [128][40] padded
    __shared__ __align__(16) __half sB[32 * 136];   // [32][136] padded

    const int tid = threadIdx.x;
    const int lane = tid & 31, warp = tid >> 5;
    const int wm = warp >> 2, wn = warp & 3;       // warp grid 2 x 4
    const int m0 = blockIdx.y * 128, n0 = blockIdx.x * 128;

    float c[4][4][4];
#pragma unroll
    for (int i = 0; i < 4; i++)
#pragma unroll
        for (int j = 0; j < 4; j++)
#pragma unroll
            for (int e = 0; e < 4; e++) c[i][j][e] = 0.f;

    for (int kb = 0; kb < HID; kb += 32) {
        // --- load A tile (128x32 fp32 -> fp16 smem) ---
#pragma unroll
        for (int t = 0; t < 4; t++) {
            int i = tid + t * 256;
            int row = i >> 3, seg = i & 7;
            float4 v = *(const float4*)&X[(size_t)(m0 + row) * HID + kb + seg * 4];
            __half2* dst = (__half2*)&sA[row * 40 + seg * 4];
            dst[0] = __floats2half2_rn(v.x, v.y);
            dst[1] = __floats2half2_rn(v.z, v.w);
        }
        // --- load B tile (32x128 fp32 -> fp16 smem) ---
#pragma unroll
        for (int t = 0; t < 4; t++) {
            int i = tid + t * 256;
            int row = i >> 5, seg = i & 31;
            float4 v = *(const float4*)&W[(size_t)(kb + row) * HID + n0 + seg * 4];
            __half2* dst = (__half2*)&sB[row * 136 + seg * 4];
            dst[0] = __floats2half2_rn(v.x, v.y);
            dst[1] = __floats2half2_rn(v.z, v.w);
        }
        __syncthreads();

#pragma unroll
        for (int ks = 0; ks < 2; ks++) {
            const int k0 = ks * 16;
            uint32_t a[4][4];
#pragma unroll
            for (int im = 0; im < 4; im++) {
                int row = wm * 64 + im * 16 + (lane & 15);
                int col = k0 + (lane >> 4) * 8;
                ldmatrix_x4(a[im][0], a[im][1], a[im][2], a[im][3],
                            smem_u32(&sA[row * 40 + col]));
            }
            uint32_t bf[4][2];
#pragma unroll
            for (int jb = 0; jb < 2; jb++) {
                int nn = wn * 32 + jb * 16 + ((lane >= 16) ? 8 : 0);
                int kr = k0 + (lane & 7) + ((lane >> 3) & 1) * 8;
                uint32_t r0, r1, r2, r3;
                ldmatrix_x4_trans(r0, r1, r2, r3, smem_u32(&sB[kr * 136 + nn]));
                bf[jb * 2][0] = r0; bf[jb * 2][1] = r1;
                bf[jb * 2 + 1][0] = r2; bf[jb * 2 + 1][1] = r3;
            }
#pragma unroll
            for (int im = 0; im < 4; im++)
#pragma unroll
                for (int jn = 0; jn < 4; jn++) mma16816(c[im][jn], a[im], bf[jn]);
        }
        __syncthreads();
    }

    // --- epilogue: +bias, fp16, permute to [b,h,s,d] ---
    const int g = lane >> 2, t4 = lane & 3;
#pragma unroll
    for (int im = 0; im < 4; im++) {
#pragma unroll
        for (int jn = 0; jn < 4; jn++) {
            int row0 = m0 + wm * 64 + im * 16 + g;
            int col = n0 + wn * 32 + jn * 8 + t4 * 2;
            float b0 = bias[col], b1 = bias[col + 1];
            int bb = row0 >> 11;            // batch (tile never crosses batch)
            int ss = row0 & (SEQ - 1);
            int hh = col >> 6, dd = col & 63;
            size_t base = ((size_t)(bb * NH + hh) * SEQ);
            *(__half2*)&out[(base + ss) * HD + dd] =
                __floats2half2_rn(c[im][jn][0] + b0, c[im][jn][1] + b1);
            *(__half2*)&out[(base + ((row0 + 8) & (SEQ - 1))) * HD + dd] =
                __floats2half2_rn(c[im][jn][2] + b0, c[im][jn][3] + b1);
        }
    }
}

// ---------------------------------------------------------------------------
// Flash attention: 1 CTA per (bh, 64-row Q tile). 4 warps x 16 rows.
// KV tiles of 64, online softmax, fp32 accumulators, fp16 mma operands.
// ---------------------------------------------------------------------------
__global__ __launch_bounds__(128) void flash_attn(const float* __restrict__ mask,
                                                  float* __restrict__ out) {
    const int bh = blockIdx.y;
    const int b = bh >> 4, h = bh & 15;
    const int q0 = blockIdx.x * 64;

    __shared__ __align__(16) __half sQ[64 * 72];
    __shared__ __align__(16) __half sK[64 * 72];
    __shared__ __align__(16) __half sV[64 * 72];
    __shared__ float sMask[64];

    const int tid = threadIdx.x, lane = tid & 31, warp = tid >> 5;
    const int g = lane >> 2, t4 = lane & 3;
    const __half* Q = g_q + (size_t)bh * SEQ * HD;
    const __half* K = g_k + (size_t)bh * SEQ * HD;
    const __half* V = g_v + (size_t)bh * SEQ * HD;

    // load Q tile
    for (int i = tid; i < 64 * 8; i += 128) {
        int row = i >> 3, seg = i & 7;
        *(uint4*)&sQ[row * 72 + seg * 8] =
            *(const uint4*)&Q[(size_t)(q0 + row) * HD + seg * 8];
    }
    __syncthreads();

    const int wr0 = warp * 16;
    uint32_t aq[4][4];
#pragma unroll
    for (int kk = 0; kk < 4; kk++) {
        int row = wr0 + (lane & 15);
        int col = kk * 16 + (lane >> 4) * 8;
        ldmatrix_x4(aq[kk][0], aq[kk][1], aq[kk][2], aq[kk][3],
                    smem_u32(&sQ[row * 72 + col]));
    }

    float o[8][4];
#pragma unroll
    for (int j = 0; j < 8; j++)
#pragma unroll
        for (int e = 0; e < 4; e++) o[j][e] = 0.f;
    float mrow[2] = {-1e30f, -1e30f};
    float lrow[2] = {0.f, 0.f};
    const float scale = 0.125f;  // 1/sqrt(64)

    for (int kv0 = 0; kv0 < SEQ; kv0 += 64) {
        __syncthreads();  // previous tile consumed
        for (int i = tid; i < 64 * 8; i += 128) {
            int row = i >> 3, seg = i & 7;
            *(uint4*)&sK[row * 72 + seg * 8] =
                *(const uint4*)&K[(size_t)(kv0 + row) * HD + seg * 8];
            *(uint4*)&sV[row * 72 + seg * 8] =
                *(const uint4*)&V[(size_t)(kv0 + row) * HD + seg * 8];
        }
        if (tid < 64) sMask[tid] = mask[(size_t)b * SEQ + kv0 + tid];
        __syncthreads();

        // ---- S = Q K^T ----
        float sc[8][4];
#pragma unroll
        for (int j = 0; j < 8; j++)
#pragma unroll
            for (int e = 0; e < 4; e++) sc[j][e] = 0.f;

#pragma unroll
        for (int kk = 0; kk < 4; kk++) {
            uint32_t bk[8][2];
#pragma unroll
            for (int jb = 0; jb < 4; jb++) {
                int row = jb * 16 + (lane & 7) + ((lane >= 16) ? 8 : 0);
                int col = kk * 16 + ((lane >> 3) & 1) * 8;
                uint32_t r0, r1, r2, r3;
                ldmatrix_x4(r0, r1, r2, r3, smem_u32(&sK[row * 72 + col]));
                bk[jb * 2][0] = r0; bk[jb * 2][1] = r1;
                bk[jb * 2 + 1][0] = r2; bk[jb * 2 + 1][1] = r3;
            }
#pragma unroll
            for (int j = 0; j < 8; j++) mma16816(sc[j], aq[kk], bk[j]);
        }

        // ---- online softmax ----
        float tmax0 = -1e30f, tmax1 = -1e30f;
#pragma unroll
        for (int j = 0; j < 8; j++) {
            float mk0 = sMask[j * 8 + t4 * 2], mk1 = sMask[j * 8 + t4 * 2 + 1];
            sc[j][0] = sc[j][0] * scale + mk0;
            sc[j][1] = sc[j][1] * scale + mk1;
            sc[j][2] = sc[j][2] * scale + mk0;
            sc[j][3] = sc[j][3] * scale + mk1;
            tmax0 = fmaxf(tmax0, fmaxf(sc[j][0], sc[j][1]));
            tmax1 = fmaxf(tmax1, fmaxf(sc[j][2], sc[j][3]));
        }
        tmax0 = fmaxf(tmax0, __shfl_xor_sync(0xffffffffu, tmax0, 1));
        tmax0 = fmaxf(tmax0, __shfl_xor_sync(0xffffffffu, tmax0, 2));
        tmax1 = fmaxf(tmax1, __shfl_xor_sync(0xffffffffu, tmax1, 1));
        tmax1 = fmaxf(tmax1, __shfl_xor_sync(0xffffffffu, tmax1, 2));

        float mnew0 = fmaxf(mrow[0], tmax0), mnew1 = fmaxf(mrow[1], tmax1);
        float alpha0 = __expf(mrow[0] - mnew0), alpha1 = __expf(mrow[1] - mnew1);
        mrow[0] = mnew0; mrow[1] = mnew1;

        float rsum0 = 0.f, rsum1 = 0.f;
        uint32_t ph[8][2];
#pragma unroll
        for (int j = 0; j < 8; j++) {
            float e0 = __expf(sc[j][0] - mnew0);
            float e1 = __expf(sc[j][1] - mnew0);
            float e2 = __expf(sc[j][2] - mnew1);
            float e3 = __expf(sc[j][3] - mnew1);
            rsum0 += e0 + e1; rsum1 += e2 + e3;
            ph[j][0] = pack_half2(e0, e1);
            ph[j][1] = pack_half2(e2, e3);
        }
        rsum0 += __shfl_xor_sync(0xffffffffu, rsum0, 1);
        rsum0 += __shfl_xor_sync(0xffffffffu, rsum0, 2);
        rsum1 += __shfl_xor_sync(0xffffffffu, rsum1, 1);
        rsum1 += __shfl_xor_sync(0xffffffffu, rsum1, 2);
        lrow[0] = lrow[0] * alpha0 + rsum0;
        lrow[1] = lrow[1] * alpha1 + rsum1;

#pragma unroll
        for (int j = 0; j < 8; j++) {
            o[j][0] *= alpha0; o[j][1] *= alpha0;
            o[j][2] *= alpha1; o[j][3] *= alpha1;
        }

        // ---- O += P V ----
#pragma unroll
        for (int kk = 0; kk < 4; kk++) {
            uint32_t ap[4] = {ph[2 * kk][0], ph[2 * kk][1],
                              ph[2 * kk + 1][0], ph[2 * kk + 1][1]};
            uint32_t bv[8][2];
#pragma unroll
            for (int jb = 0; jb < 4; jb++) {
                int row = kk * 16 + (lane & 7) + ((lane >> 3) & 1) * 8;
                int col = jb * 16 + ((lane >= 16) ? 8 : 0);
                uint32_t r0, r1, r2, r3;
                ldmatrix_x4_trans(r0, r1, r2, r3, smem_u32(&sV[row * 72 + col]));
                bv[jb * 2][0] = r0; bv[jb * 2][1] = r1;
                bv[jb * 2 + 1][0] = r2; bv[jb * 2 + 1][1] = r3;
            }
#pragma unroll
            for (int j = 0; j < 8; j++) mma16816(o[j], ap, bv[j]);
        }
    }

    // ---- epilogue: normalize, write fp32 [b, s, h*64+d] ----
    float inv0 = 1.f / lrow[0], inv1 = 1.f / lrow[1];
#pragma unroll
    for (int j = 0; j < 8; j++) {
        int row0 = q0 + wr0 + g;
        int col = j * 8 + t4 * 2;
        size_t base0 = ((size_t)(b * SEQ + row0)) * HID + h * 64 + col;
        size_t base1 = ((size_t)(b * SEQ + row0 + 8)) * HID + h * 64 + col;
        float2 v0 = make_float2(o[j][0] * inv0, o[j][1] * inv0);
        float2 v1 = make_float2(o[j][2] * inv1, o[j][3] * inv1);
        *(float2*)&out[base0] = v0;
        *(float2*)&out[base1] = v1;
    }
}

// ---------------------------------------------------------------------------
extern "C" void kernel_launch(void* const* d_in, const int* in_sizes, int n_in,
                              void* d_out, int out_size) {
    const float* former = (const float*)d_in[0];
    const float* latter = (const float*)d_in[1];
    const float* mask   = (const float*)d_in[2];
    const float* Wq = (const float*)d_in[3];
    const float* bq = (const float*)d_in[4];
    const float* Wk = (const float*)d_in[5];
    const float* bk = (const float*)d_in[6];
    const float* Wv = (const float*)d_in[7];
    const float* bv = (const float*)d_in[8];

    dim3 g1(HID / 128, (NB * SEQ) / 128, 3);
    qkv_gemm<<<g1, 256>>>(former, latter, Wq, bq, Wk, bk, Wv, bv);

    dim3 g2(SEQ / 64, NB * NH);
    flash_attn<<<g2, 128>>>(mask, (float*)d_out);
}

// round 3
// speedup vs baseline: 1.2221x; 1.2221x over previous
#include <cuda_runtime.h>
#include <cuda_fp16.h>
#include <cstdint>

#define NB 2
#define NH 16
#define HD 64
#define SEQ 2048
#define HID 1024

// fp16 scratch: Q/K/V in [b, h, s, d] layout (8 MB each, static => allocation-free)
__device__ __half g_q[(size_t)NB * NH * SEQ * HD];
__device__ __half g_k[(size_t)NB * NH * SEQ * HD];
__device__ __half g_v[(size_t)NB * NH * SEQ * HD];

// ---------------------------------------------------------------------------
// PTX helpers
// ---------------------------------------------------------------------------
__device__ __forceinline__ uint32_t smem_u32(const void* p) {
    return (uint32_t)__cvta_generic_to_shared(p);
}

__device__ __forceinline__ void ldmatrix_x4(uint32_t& r0, uint32_t& r1, uint32_t& r2,
                                            uint32_t& r3, uint32_t addr) {
    asm volatile("ldmatrix.sync.aligned.m8n8.x4.shared.b16 {%0,%1,%2,%3},[%4];\n"
                 : "=r"(r0), "=r"(r1), "=r"(r2), "=r"(r3) : "r"(addr));
}

__device__ __forceinline__ void ldmatrix_x4_trans(uint32_t& r0, uint32_t& r1, uint32_t& r2,
                                                  uint32_t& r3, uint32_t addr) {
    asm volatile("ldmatrix.sync.aligned.m8n8.x4.trans.shared.b16 {%0,%1,%2,%3},[%4];\n"
                 : "=r"(r0), "=r"(r1), "=r"(r2), "=r"(r3) : "r"(addr));
}

__device__ __forceinline__ void mma16816(float* c, const uint32_t* a, const uint32_t* b) {
    asm volatile(
        "mma.sync.aligned.m16n8k16.row.col.f32.f16.f16.f32 "
        "{%0,%1,%2,%3},{%4,%5,%6,%7},{%8,%9},{%0,%1,%2,%3};\n"
        : "+f"(c[0]), "+f"(c[1]), "+f"(c[2]), "+f"(c[3])
        : "r"(a[0]), "r"(a[1]), "r"(a[2]), "r"(a[3]), "r"(b[0]), "r"(b[1]));
}

__device__ __forceinline__ uint32_t pack_half2(float x, float y) {
    __half2 h = __floats2half2_rn(x, y);
    return *(uint32_t*)&h;
}

__device__ __forceinline__ void cp_async16(uint32_t dst, const void* src) {
    asm volatile("cp.async.cg.shared.global [%0], [%1], 16;\n" ::"r"(dst), "l"(src));
}
__device__ __forceinline__ void cp_commit() {
    asm volatile("cp.async.commit_group;\n" ::: "memory");
}
__device__ __forceinline__ void cp_wait1() {
    asm volatile("cp.async.wait_group 1;\n" ::: "memory");
}
__device__ __forceinline__ void cp_wait0() {
    asm volatile("cp.async.wait_group 0;\n" ::: "memory");
}

// ---------------------------------------------------------------------------
// QKV projection GEMM: Y = X @ W + b, output fp16 in [b,h,s,d] scratch.
// M=4096, N=1024, K=1024. CTA tile 128x128x32, 8 warps (2x4), warp tile 64x32.
// gridDim.z selects Q / K / V. (Measured ~192 TF/s — near mma.sync ceiling;
// left unchanged this round.)
// ---------------------------------------------------------------------------
__global__ __launch_bounds__(256) void qkv_gemm(
    const float* __restrict__ former, const float* __restrict__ latter,
    const float* __restrict__ Wq, const float* __restrict__ bq,
    const float* __restrict__ Wk, const float* __restrict__ bk,
    const float* __restrict__ Wv, const float* __restrict__ bv) {
    const int which = blockIdx.z;
    const float* X    = (which == 0) ? former : latter;
    const float* W    = (which == 0) ? Wq : (which == 1) ? Wk : Wv;
    const float* bias = (which == 0) ? bq : (which == 1) ? bk : bv;
    __half* out       = (which == 0) ? g_q : (which == 1) ? g_k : g_v;

    __shared__ __align__(16) __half sA[128 * 40];   // [128][40] padded
    __shared__ __align__(16) __half sB[32 * 136];   // [32][136] padded

    const int tid = threadIdx.x;
    const int lane = tid & 31, warp = tid >> 5;
    const int wm = warp >> 2, wn = warp & 3;       // warp grid 2 x 4
    const int m0 = blockIdx.y * 128, n0 = blockIdx.x * 128;

    float c[4][4][4];
#pragma unroll
    for (int i = 0; i < 4; i++)
#pragma unroll
        for (int j = 0; j < 4; j++)
#pragma unroll
            for (int e = 0; e < 4; e++) c[i][j][e] = 0.f;

    for (int kb = 0; kb < HID; kb += 32) {
        // --- load A tile (128x32 fp32 -> fp16 smem) ---
#pragma unroll
        for (int t = 0; t < 4; t++) {
            int i = tid + t * 256;
            int row = i >> 3, seg = i & 7;
            float4 v = *(const float4*)&X[(size_t)(m0 + row) * HID + kb + seg * 4];
            __half2* dst = (__half2*)&sA[row * 40 + seg * 4];
            dst[0] = __floats2half2_rn(v.x, v.y);
            dst[1] = __floats2half2_rn(v.z, v.w);
        }
        // --- load B tile (32x128 fp32 -> fp16 smem) ---
#pragma unroll
        for (int t = 0; t < 4; t++) {
            int i = tid + t * 256;
            int row = i >> 5, seg = i & 31;
            float4 v = *(const float4*)&W[(size_t)(kb + row) * HID + n0 + seg * 4];
            __half2* dst = (__half2*)&sB[row * 136 + seg * 4];
            dst[0] = __floats2half2_rn(v.x, v.y);
            dst[1] = __floats2half2_rn(v.z, v.w);
        }
        __syncthreads();

#pragma unroll
        for (int ks = 0; ks < 2; ks++) {
            const int k0 = ks * 16;
            uint32_t a[4][4];
#pragma unroll
            for (int im = 0; im < 4; im++) {
                int row = wm * 64 + im * 16 + (lane & 15);
                int col = k0 + (lane >> 4) * 8;
                ldmatrix_x4(a[im][0], a[im][1], a[im][2], a[im][3],
                            smem_u32(&sA[row * 40 + col]));
            }
            uint32_t bf[4][2];
#pragma unroll
            for (int jb = 0; jb < 2; jb++) {
                int nn = wn * 32 + jb * 16 + ((lane >= 16) ? 8 : 0);
                int kr = k0 + (lane & 7) + ((lane >> 3) & 1) * 8;
                uint32_t r0, r1, r2, r3;
                ldmatrix_x4_trans(r0, r1, r2, r3, smem_u32(&sB[kr * 136 + nn]));
                bf[jb * 2][0] = r0; bf[jb * 2][1] = r1;
                bf[jb * 2 + 1][0] = r2; bf[jb * 2 + 1][1] = r3;
            }
#pragma unroll
            for (int im = 0; im < 4; im++)
#pragma unroll
                for (int jn = 0; jn < 4; jn++) mma16816(c[im][jn], a[im], bf[jn]);
        }
        __syncthreads();
    }

    // --- epilogue: +bias, fp16, permute to [b,h,s,d] ---
    const int g = lane >> 2, t4 = lane & 3;
#pragma unroll
    for (int im = 0; im < 4; im++) {
#pragma unroll
        for (int jn = 0; jn < 4; jn++) {
            int row0 = m0 + wm * 64 + im * 16 + g;
            int col = n0 + wn * 32 + jn * 8 + t4 * 2;
            float b0 = bias[col], b1 = bias[col + 1];
            int bb = row0 >> 11;            // batch (tile never crosses batch)
            int ss = row0 & (SEQ - 1);
            int hh = col >> 6, dd = col & 63;
            size_t base = ((size_t)(bb * NH + hh) * SEQ);
            *(__half2*)&out[(base + ss) * HD + dd] =
                __floats2half2_rn(c[im][jn][0] + b0, c[im][jn][1] + b1);
            *(__half2*)&out[(base + ((row0 + 8) & (SEQ - 1))) * HD + dd] =
                __floats2half2_rn(c[im][jn][2] + b0, c[im][jn][3] + b1);
        }
    }
}

// ---------------------------------------------------------------------------
// Flash attention: 1 CTA per (bh, 64-row Q tile). 4 warps x 16 rows.
// KV tiles of 64, online softmax, fp32 accumulators, fp16 mma operands.
// 2-stage cp.async double buffering of K/V/mask tiles.
// ---------------------------------------------------------------------------
__global__ __launch_bounds__(128) void flash_attn(const float* __restrict__ mask,
                                                  float* __restrict__ out) {
    const int bh = blockIdx.y;
    const int b = bh >> 4, h = bh & 15;
    const int q0 = blockIdx.x * 64;

    __shared__ __align__(16) __half sQ[64 * 72];
    __shared__ __align__(16) __half sK[2][64 * 72];
    __shared__ __align__(16) __half sV[2][64 * 72];
    __shared__ __align__(16) float sMask[2][64];

    const int tid = threadIdx.x, lane = tid & 31, warp = tid >> 5;
    const int g = lane >> 2, t4 = lane & 3;
    const __half* Q = g_q + (size_t)bh * SEQ * HD;
    const __half* K = g_k + (size_t)bh * SEQ * HD;
    const __half* V = g_v + (size_t)bh * SEQ * HD;
    const float* maskRow = mask + (size_t)b * SEQ;

    // prefetch helper: stage KV tile `tile` into buffer `buf`
    auto prefetch = [&](int tile, int buf) {
        const __half* Kt = K + (size_t)tile * 64 * HD;
        const __half* Vt = V + (size_t)tile * 64 * HD;
#pragma unroll
        for (int t = 0; t < 4; t++) {
            int cix = tid + t * 128;
            int row = cix >> 3, seg = cix & 7;   // 8 x 16B chunks per 64-half row
            cp_async16(smem_u32(&sK[buf][row * 72 + seg * 8]), &Kt[row * 64 + seg * 8]);
            cp_async16(smem_u32(&sV[buf][row * 72 + seg * 8]), &Vt[row * 64 + seg * 8]);
        }
        if (tid < 16)
            cp_async16(smem_u32(&sMask[buf][tid * 4]), &maskRow[tile * 64 + tid * 4]);
        cp_commit();
    };

    prefetch(0, 0);

    // load Q tile (once, synchronous is fine; overlaps with cp.async group 0)
    for (int i = tid; i < 64 * 8; i += 128) {
        int row = i >> 3, seg = i & 7;
        *(uint4*)&sQ[row * 72 + seg * 8] =
            *(const uint4*)&Q[(size_t)(q0 + row) * HD + seg * 8];
    }
    __syncthreads();

    const int wr0 = warp * 16;
    uint32_t aq[4][4];
#pragma unroll
    for (int kk = 0; kk < 4; kk++) {
        int row = wr0 + (lane & 15);
        int col = kk * 16 + (lane >> 4) * 8;
        ldmatrix_x4(aq[kk][0], aq[kk][1], aq[kk][2], aq[kk][3],
                    smem_u32(&sQ[row * 72 + col]));
    }

    float o[8][4];
#pragma unroll
    for (int j = 0; j < 8; j++)
#pragma unroll
        for (int e = 0; e < 4; e++) o[j][e] = 0.f;
    float mrow[2] = {-1e30f, -1e30f};
    float lrow[2] = {0.f, 0.f};
    const float scale = 0.125f;  // 1/sqrt(64)

    const int NT = SEQ / 64;  // 32 tiles
    for (int it = 0; it < NT; it++) {
        const int cur = it & 1;
        if (it + 1 < NT) {
            prefetch(it + 1, cur ^ 1);
            cp_wait1();
        } else {
            cp_wait0();
        }
        __syncthreads();

        const __half* tK = sK[cur];
        const __half* tV = sV[cur];
        const float* tM = sMask[cur];

        // ---- S = Q K^T ----
        float sc[8][4];
#pragma unroll
        for (int j = 0; j < 8; j++)
#pragma unroll
            for (int e = 0; e < 4; e++) sc[j][e] = 0.f;

#pragma unroll
        for (int kk = 0; kk < 4; kk++) {
            uint32_t bk[8][2];
#pragma unroll
            for (int jb = 0; jb < 4; jb++) {
                int row = jb * 16 + (lane & 7) + ((lane >= 16) ? 8 : 0);
                int col = kk * 16 + ((lane >> 3) & 1) * 8;
                uint32_t r0, r1, r2, r3;
                ldmatrix_x4(r0, r1, r2, r3, smem_u32(&tK[row * 72 + col]));
                bk[jb * 2][0] = r0; bk[jb * 2][1] = r1;
                bk[jb * 2 + 1][0] = r2; bk[jb * 2 + 1][1] = r3;
            }
#pragma unroll
            for (int j = 0; j < 8; j++) mma16816(sc[j], aq[kk], bk[j]);
        }

        // ---- online softmax ----
        float tmax0 = -1e30f, tmax1 = -1e30f;
#pragma unroll
        for (int j = 0; j < 8; j++) {
            float mk0 = tM[j * 8 + t4 * 2], mk1 = tM[j * 8 + t4 * 2 + 1];
            sc[j][0] = sc[j][0] * scale + mk0;
            sc[j][1] = sc[j][1] * scale + mk1;
            sc[j][2] = sc[j][2] * scale + mk0;
            sc[j][3] = sc[j][3] * scale + mk1;
            tmax0 = fmaxf(tmax0, fmaxf(sc[j][0], sc[j][1]));
            tmax1 = fmaxf(tmax1, fmaxf(sc[j][2], sc[j][3]));
        }
        tmax0 = fmaxf(tmax0, __shfl_xor_sync(0xffffffffu, tmax0, 1));
        tmax0 = fmaxf(tmax0, __shfl_xor_sync(0xffffffffu, tmax0, 2));
        tmax1 = fmaxf(tmax1, __shfl_xor_sync(0xffffffffu, tmax1, 1));
        tmax1 = fmaxf(tmax1, __shfl_xor_sync(0xffffffffu, tmax1, 2));

        float mnew0 = fmaxf(mrow[0], tmax0), mnew1 = fmaxf(mrow[1], tmax1);
        float alpha0 = __expf(mrow[0] - mnew0), alpha1 = __expf(mrow[1] - mnew1);
        mrow[0] = mnew0; mrow[1] = mnew1;

        float rsum0 = 0.f, rsum1 = 0.f;
        uint32_t ph[8][2];
#pragma unroll
        for (int j = 0; j < 8; j++) {
            float e0 = __expf(sc[j][0] - mnew0);
            float e1 = __expf(sc[j][1] - mnew0);
            float e2 = __expf(sc[j][2] - mnew1);
            float e3 = __expf(sc[j][3] - mnew1);
            rsum0 += e0 + e1; rsum1 += e2 + e3;
            ph[j][0] = pack_half2(e0, e1);
            ph[j][1] = pack_half2(e2, e3);
        }
        rsum0 += __shfl_xor_sync(0xffffffffu, rsum0, 1);
        rsum0 += __shfl_xor_sync(0xffffffffu, rsum0, 2);
        rsum1 += __shfl_xor_sync(0xffffffffu, rsum1, 1);
        rsum1 += __shfl_xor_sync(0xffffffffu, rsum1, 2);
        lrow[0] = lrow[0] * alpha0 + rsum0;
        lrow[1] = lrow[1] * alpha1 + rsum1;

#pragma unroll
        for (int j = 0; j < 8; j++) {
            o[j][0] *= alpha0; o[j][1] *= alpha0;
            o[j][2] *= alpha1; o[j][3] *= alpha1;
        }

        // ---- O += P V ----
#pragma unroll
        for (int kk = 0; kk < 4; kk++) {
            uint32_t ap[4] = {ph[2 * kk][0], ph[2 * kk][1],
                              ph[2 * kk + 1][0], ph[2 * kk + 1][1]};
            uint32_t bv[8][2];
#pragma unroll
            for (int jb = 0; jb < 4; jb++) {
                int row = kk * 16 + (lane & 7) + ((lane >> 3) & 1) * 8;
                int col = jb * 16 + ((lane >= 16) ? 8 : 0);
                uint32_t r0, r1, r2, r3;
                ldmatrix_x4_trans(r0, r1, r2, r3, smem_u32(&tV[row * 72 + col]));
                bv[jb * 2][0] = r0; bv[jb * 2][1] = r1;
                bv[jb * 2 + 1][0] = r2; bv[jb * 2 + 1][1] = r3;
            }
#pragma unroll
            for (int j = 0; j < 8; j++) mma16816(o[j], ap, bv[j]);
        }
        __syncthreads();  // protect buf `cur` before it is re-filled at it+1
    }

    // ---- epilogue: normalize, write fp32 [b, s, h*64+d] ----
    float inv0 = 1.f / lrow[0], inv1 = 1.f / lrow[1];
#pragma unroll
    for (int j = 0; j < 8; j++) {
        int row0 = q0 + wr0 + g;
        int col = j * 8 + t4 * 2;
        size_t base0 = ((size_t)(b * SEQ + row0)) * HID + h * 64 + col;
        size_t base1 = ((size_t)(b * SEQ + row0 + 8)) * HID + h * 64 + col;
        float2 v0 = make_float2(o[j][0] * inv0, o[j][1] * inv0);
        float2 v1 = make_float2(o[j][2] * inv1, o[j][3] * inv1);
        *(float2*)&out[base0] = v0;
        *(float2*)&out[base1] = v1;
    }
}

// ---------------------------------------------------------------------------
extern "C" void kernel_launch(void* const* d_in, const int* in_sizes, int n_in,
                              void* d_out, int out_size) {
    const float* former = (const float*)d_in[0];
    const float* latter = (const float*)d_in[1];
    const float* mask   = (const float*)d_in[2];
    const float* Wq = (const float*)d_in[3];
    const float* bq = (const float*)d_in[4];
    const float* Wk = (const float*)d_in[5];
    const float* bk = (const float*)d_in[6];
    const float* Wv = (const float*)d_in[7];
    const float* bv = (const float*)d_in[8];

    dim3 g1(HID / 128, (NB * SEQ) / 128, 3);
    qkv_gemm<<<g1, 256>>>(former, latter, Wq, bq, Wk, bk, Wv, bv);

    dim3 g2(SEQ / 64, NB * NH);
    flash_attn<<<g2, 128>>>(mask, (float*)d_out);
}

// round 4
// speedup vs baseline: 1.4007x; 1.1461x over previous
#include <cuda_runtime.h>
#include <cuda_fp16.h>
#include <cstdint>

#define NB 2
#define NH 16
#define HD 64
#define SEQ 2048
#define HID 1024

// fp16 scratch: Q/K/V in [b, h, s, d] layout (8 MB each, static => allocation-free)
__device__ __half g_q[(size_t)NB * NH * SEQ * HD];
__device__ __half g_k[(size_t)NB * NH * SEQ * HD];
__device__ __half g_v[(size_t)NB * NH * SEQ * HD];

// fp16 copies of inputs: former[4M] | latter[4M] | Wq[1M] | Wk[1M] | Wv[1M]
#define CVT_FORMER 0
#define CVT_LATTER ((size_t)NB * SEQ * HID)
#define CVT_W      ((size_t)2 * NB * SEQ * HID)
#define CVT_TOTAL  (CVT_W + (size_t)3 * HID * HID)
__device__ __half g_cvt[CVT_TOTAL];

// ---------------------------------------------------------------------------
// PTX helpers
// ---------------------------------------------------------------------------
__device__ __forceinline__ uint32_t smem_u32(const void* p) {
    return (uint32_t)__cvta_generic_to_shared(p);
}

__device__ __forceinline__ void ldmatrix_x4(uint32_t& r0, uint32_t& r1, uint32_t& r2,
                                            uint32_t& r3, uint32_t addr) {
    asm volatile("ldmatrix.sync.aligned.m8n8.x4.shared.b16 {%0,%1,%2,%3},[%4];\n"
                 : "=r"(r0), "=r"(r1), "=r"(r2), "=r"(r3) : "r"(addr));
}

__device__ __forceinline__ void ldmatrix_x4_trans(uint32_t& r0, uint32_t& r1, uint32_t& r2,
                                                  uint32_t& r3, uint32_t addr) {
    asm volatile("ldmatrix.sync.aligned.m8n8.x4.trans.shared.b16 {%0,%1,%2,%3},[%4];\n"
                 : "=r"(r0), "=r"(r1), "=r"(r2), "=r"(r3) : "r"(addr));
}

__device__ __forceinline__ void mma16816(float* c, const uint32_t* a, const uint32_t* b) {
    asm volatile(
        "mma.sync.aligned.m16n8k16.row.col.f32.f16.f16.f32 "
        "{%0,%1,%2,%3},{%4,%5,%6,%7},{%8,%9},{%0,%1,%2,%3};\n"
        : "+f"(c[0]), "+f"(c[1]), "+f"(c[2]), "+f"(c[3])
        : "r"(a[0]), "r"(a[1]), "r"(a[2]), "r"(a[3]), "r"(b[0]), "r"(b[1]));
}

__device__ __forceinline__ uint32_t pack_half2(float x, float y) {
    __half2 h = __floats2half2_rn(x, y);
    return *(uint32_t*)&h;
}

__device__ __forceinline__ void cp_async16(uint32_t dst, const void* src) {
    asm volatile("cp.async.cg.shared.global [%0], [%1], 16;\n" ::"r"(dst), "l"(src));
}
__device__ __forceinline__ void cp_commit() {
    asm volatile("cp.async.commit_group;\n" ::: "memory");
}
__device__ __forceinline__ void cp_wait1() {
    asm volatile("cp.async.wait_group 1;\n" ::: "memory");
}
__device__ __forceinline__ void cp_wait0() {
    asm volatile("cp.async.wait_group 0;\n" ::: "memory");
}

// ---------------------------------------------------------------------------
// Convert kernel: fp32 inputs -> fp16 staging (memory-bound, ~10 us)
// Linear layout: former | latter | Wq | Wk | Wv   (element counts above)
// ---------------------------------------------------------------------------
__global__ __launch_bounds__(256) void convert_inputs(
    const float* __restrict__ former, const float* __restrict__ latter,
    const float* __restrict__ Wq, const float* __restrict__ Wk,
    const float* __restrict__ Wv) {
    size_t i4 = ((size_t)blockIdx.x * 256 + threadIdx.x) * 4;  // element index (x4)
    if (i4 >= CVT_TOTAL) return;

    const float* src;
    size_t off;
    if (i4 < CVT_LATTER)      { src = former; off = i4; }
    else if (i4 < CVT_W)      { src = latter; off = i4 - CVT_LATTER; }
    else {
        size_t w = i4 - CVT_W;
        size_t wsz = (size_t)HID * HID;
        if (w < wsz)            { src = Wq; off = w; }
        else if (w < 2 * wsz)   { src = Wk; off = w - wsz; }
        else                    { src = Wv; off = w - 2 * wsz; }
    }
    float4 v = *(const float4*)&src[off];
    __half2* dst = (__half2*)&g_cvt[i4];
    dst[0] = __floats2half2_rn(v.x, v.y);
    dst[1] = __floats2half2_rn(v.z, v.w);
}

// ---------------------------------------------------------------------------
// QKV projection GEMM (fp16 in, fp32 accum): Y = X @ W + b, out fp16 [b,h,s,d].
// M=4096, N=1024, K=1024. CTA tile 128x128x32, 8 warps (2x4), warp tile 64x32.
// Round 4: pure fp16 operands + 2-stage cp.async double buffering.
// gridDim.z selects Q / K / V.
// ---------------------------------------------------------------------------
__global__ __launch_bounds__(256) void qkv_gemm(
    const float* __restrict__ bq, const float* __restrict__ bk,
    const float* __restrict__ bv) {
    const int which = blockIdx.z;
    const __half* X    = g_cvt + ((which == 0) ? CVT_FORMER : CVT_LATTER);
    const __half* W    = g_cvt + CVT_W + (size_t)which * HID * HID;
    const float* bias  = (which == 0) ? bq : (which == 1) ? bk : bv;
    __half* out        = (which == 0) ? g_q : (which == 1) ? g_k : g_v;

    __shared__ __align__(16) __half sA[2][128 * 40];   // [128][40] padded
    __shared__ __align__(16) __half sB[2][32 * 136];   // [32][136] padded

    const int tid = threadIdx.x;
    const int lane = tid & 31, warp = tid >> 5;
    const int wm = warp >> 2, wn = warp & 3;       // warp grid 2 x 4
    const int m0 = blockIdx.y * 128, n0 = blockIdx.x * 128;

    // stage loader: K-block kb (x32) into buffer buf. 1024 x 16B chunks, 4/thread.
    auto prefetch = [&](int kb, int buf) {
        // A: 128 rows x 4 chunks (32 halves/row)
#pragma unroll
        for (int t = 0; t < 2; t++) {
            int i = tid + t * 256;           // 0..511
            int row = i >> 2, seg = i & 3;
            cp_async16(smem_u32(&sA[buf][row * 40 + seg * 8]),
                       &X[(size_t)(m0 + row) * HID + kb + seg * 8]);
        }
        // B: 32 rows x 16 chunks (128 halves/row)
#pragma unroll
        for (int t = 0; t < 2; t++) {
            int i = tid + t * 256;           // 0..511
            int row = i >> 4, seg = i & 15;
            cp_async16(smem_u32(&sB[buf][row * 136 + seg * 8]),
                       &W[(size_t)(kb + row) * HID + n0 + seg * 8]);
        }
        cp_commit();
    };

    float c[4][4][4];
#pragma unroll
    for (int i = 0; i < 4; i++)
#pragma unroll
        for (int j = 0; j < 4; j++)
#pragma unroll
            for (int e = 0; e < 4; e++) c[i][j][e] = 0.f;

    prefetch(0, 0);

    const int NKB = HID / 32;  // 32 k-blocks
    for (int it = 0; it < NKB; it++) {
        const int cur = it & 1;
        if (it + 1 < NKB) {
            prefetch((it + 1) * 32, cur ^ 1);
            cp_wait1();
        } else {
            cp_wait0();
        }
        __syncthreads();

        const __half* tA = sA[cur];
        const __half* tB = sB[cur];

#pragma unroll
        for (int ks = 0; ks < 2; ks++) {
            const int k0 = ks * 16;
            uint32_t a[4][4];
#pragma unroll
            for (int im = 0; im < 4; im++) {
                int row = wm * 64 + im * 16 + (lane & 15);
                int col = k0 + (lane >> 4) * 8;
                ldmatrix_x4(a[im][0], a[im][1], a[im][2], a[im][3],
                            smem_u32(&tA[row * 40 + col]));
            }
            uint32_t bf[4][2];
#pragma unroll
            for (int jb = 0; jb < 2; jb++) {
                int nn = wn * 32 + jb * 16 + ((lane >= 16) ? 8 : 0);
                int kr = k0 + (lane & 7) + ((lane >> 3) & 1) * 8;
                uint32_t r0, r1, r2, r3;
                ldmatrix_x4_trans(r0, r1, r2, r3, smem_u32(&tB[kr * 136 + nn]));
                bf[jb * 2][0] = r0; bf[jb * 2][1] = r1;
                bf[jb * 2 + 1][0] = r2; bf[jb * 2 + 1][1] = r3;
            }
#pragma unroll
            for (int im = 0; im < 4; im++)
#pragma unroll
                for (int jn = 0; jn < 4; jn++) mma16816(c[im][jn], a[im], bf[jn]);
        }
        __syncthreads();   // protect buf `cur` before it is re-filled at it+1
    }

    // --- epilogue: +bias, fp16, permute to [b,h,s,d] ---
    const int g = lane >> 2, t4 = lane & 3;
#pragma unroll
    for (int im = 0; im < 4; im++) {
#pragma unroll
        for (int jn = 0; jn < 4; jn++) {
            int row0 = m0 + wm * 64 + im * 16 + g;
            int col = n0 + wn * 32 + jn * 8 + t4 * 2;
            float b0 = bias[col], b1 = bias[col + 1];
            int bb = row0 >> 11;            // batch (tile never crosses batch)
            int ss = row0 & (SEQ - 1);
            int hh = col >> 6, dd = col & 63;
            size_t base = ((size_t)(bb * NH + hh) * SEQ);
            *(__half2*)&out[(base + ss) * HD + dd] =
                __floats2half2_rn(c[im][jn][0] + b0, c[im][jn][1] + b1);
            *(__half2*)&out[(base + ((row0 + 8) & (SEQ - 1))) * HD + dd] =
                __floats2half2_rn(c[im][jn][2] + b0, c[im][jn][3] + b1);
        }
    }
}

// ---------------------------------------------------------------------------
// Flash attention: 1 CTA per (bh, 64-row Q tile). 4 warps x 16 rows.
// KV tiles of 64, online softmax, fp32 accumulators, fp16 mma operands.
// 2-stage cp.async double buffering of K/V/mask tiles. (unchanged from R3)
// ---------------------------------------------------------------------------
__global__ __launch_bounds__(128) void flash_attn(const float* __restrict__ mask,
                                                  float* __restrict__ out) {
    const int bh = blockIdx.y;
    const int b = bh >> 4, h = bh & 15;
    const int q0 = blockIdx.x * 64;

    __shared__ __align__(16) __half sQ[64 * 72];
    __shared__ __align__(16) __half sK[2][64 * 72];
    __shared__ __align__(16) __half sV[2][64 * 72];
    __shared__ __align__(16) float sMask[2][64];

    const int tid = threadIdx.x, lane = tid & 31, warp = tid >> 5;
    const int g = lane >> 2, t4 = lane & 3;
    const __half* Q = g_q + (size_t)bh * SEQ * HD;
    const __half* K = g_k + (size_t)bh * SEQ * HD;
    const __half* V = g_v + (size_t)bh * SEQ * HD;
    const float* maskRow = mask + (size_t)b * SEQ;

    auto prefetch = [&](int tile, int buf) {
        const __half* Kt = K + (size_t)tile * 64 * HD;
        const __half* Vt = V + (size_t)tile * 64 * HD;
#pragma unroll
        for (int t = 0; t < 4; t++) {
            int cix = tid + t * 128;
            int row = cix >> 3, seg = cix & 7;   // 8 x 16B chunks per 64-half row
            cp_async16(smem_u32(&sK[buf][row * 72 + seg * 8]), &Kt[row * 64 + seg * 8]);
            cp_async16(smem_u32(&sV[buf][row * 72 + seg * 8]), &Vt[row * 64 + seg * 8]);
        }
        if (tid < 16)
            cp_async16(smem_u32(&sMask[buf][tid * 4]), &maskRow[tile * 64 + tid * 4]);
        cp_commit();
    };

    prefetch(0, 0);

    // load Q tile (once; overlaps with cp.async group 0)
    for (int i = tid; i < 64 * 8; i += 128) {
        int row = i >> 3, seg = i & 7;
        *(uint4*)&sQ[row * 72 + seg * 8] =
            *(const uint4*)&Q[(size_t)(q0 + row) * HD + seg * 8];
    }
    __syncthreads();

    const int wr0 = warp * 16;
    uint32_t aq[4][4];
#pragma unroll
    for (int kk = 0; kk < 4; kk++) {
        int row = wr0 + (lane & 15);
        int col = kk * 16 + (lane >> 4) * 8;
        ldmatrix_x4(aq[kk][0], aq[kk][1], aq[kk][2], aq[kk][3],
                    smem_u32(&sQ[row * 72 + col]));
    }

    float o[8][4];
#pragma unroll
    for (int j = 0; j < 8; j++)
#pragma unroll
        for (int e = 0; e < 4; e++) o[j][e] = 0.f;
    float mrow[2] = {-1e30f, -1e30f};
    float lrow[2] = {0.f, 0.f};
    const float scale = 0.125f;  // 1/sqrt(64)

    const int NT = SEQ / 64;  // 32 tiles
    for (int it = 0; it < NT; it++) {
        const int cur = it & 1;
        if (it + 1 < NT) {
            prefetch(it + 1, cur ^ 1);
            cp_wait1();
        } else {
            cp_wait0();
        }
        __syncthreads();

        const __half* tK = sK[cur];
        const __half* tV = sV[cur];
        const float* tM = sMask[cur];

        // ---- S = Q K^T ----
        float sc[8][4];
#pragma unroll
        for (int j = 0; j < 8; j++)
#pragma unroll
            for (int e = 0; e < 4; e++) sc[j][e] = 0.f;

#pragma unroll
        for (int kk = 0; kk < 4; kk++) {
            uint32_t bk[8][2];
#pragma unroll
            for (int jb = 0; jb < 4; jb++) {
                int row = jb * 16 + (lane & 7) + ((lane >= 16) ? 8 : 0);
                int col = kk * 16 + ((lane >> 3) & 1) * 8;
                uint32_t r0, r1, r2, r3;
                ldmatrix_x4(r0, r1, r2, r3, smem_u32(&tK[row * 72 + col]));
                bk[jb * 2][0] = r0; bk[jb * 2][1] = r1;
                bk[jb * 2 + 1][0] = r2; bk[jb * 2 + 1][1] = r3;
            }
#pragma unroll
            for (int j = 0; j < 8; j++) mma16816(sc[j], aq[kk], bk[j]);
        }

        // ---- online softmax ----
        float tmax0 = -1e30f, tmax1 = -1e30f;
#pragma unroll
        for (int j = 0; j < 8; j++) {
            float mk0 = tM[j * 8 + t4 * 2], mk1 = tM[j * 8 + t4 * 2 + 1];
            sc[j][0] = sc[j][0] * scale + mk0;
            sc[j][1] = sc[j][1] * scale + mk1;
            sc[j][2] = sc[j][2] * scale + mk0;
            sc[j][3] = sc[j][3] * scale + mk1;
            tmax0 = fmaxf(tmax0, fmaxf(sc[j][0], sc[j][1]));
            tmax1 = fmaxf(tmax1, fmaxf(sc[j][2], sc[j][3]));
        }
        tmax0 = fmaxf(tmax0, __shfl_xor_sync(0xffffffffu, tmax0, 1));
        tmax0 = fmaxf(tmax0, __shfl_xor_sync(0xffffffffu, tmax0, 2));
        tmax1 = fmaxf(tmax1, __shfl_xor_sync(0xffffffffu, tmax1, 1));
        tmax1 = fmaxf(tmax1, __shfl_xor_sync(0xffffffffu, tmax1, 2));

        float mnew0 = fmaxf(mrow[0], tmax0), mnew1 = fmaxf(mrow[1], tmax1);
        float alpha0 = __expf(mrow[0] - mnew0), alpha1 = __expf(mrow[1] - mnew1);
        mrow[0] = mnew0; mrow[1] = mnew1;

        float rsum0 = 0.f, rsum1 = 0.f;
        uint32_t ph[8][2];
#pragma unroll
        for (int j = 0; j < 8; j++) {
            float e0 = __expf(sc[j][0] - mnew0);
            float e1 = __expf(sc[j][1] - mnew0);
            float e2 = __expf(sc[j][2] - mnew1);
            float e3 = __expf(sc[j][3] - mnew1);
            rsum0 += e0 + e1; rsum1 += e2 + e3;
            ph[j][0] = pack_half2(e0, e1);
            ph[j][1] = pack_half2(e2, e3);
        }
        rsum0 += __shfl_xor_sync(0xffffffffu, rsum0, 1);
        rsum0 += __shfl_xor_sync(0xffffffffu, rsum0, 2);
        rsum1 += __shfl_xor_sync(0xffffffffu, rsum1, 1);
        rsum1 += __shfl_xor_sync(0xffffffffu, rsum1, 2);
        lrow[0] = lrow[0] * alpha0 + rsum0;
        lrow[1] = lrow[1] * alpha1 + rsum1;

#pragma unroll
        for (int j = 0; j < 8; j++) {
            o[j][0] *= alpha0; o[j][1] *= alpha0;
            o[j][2] *= alpha1; o[j][3] *= alpha1;
        }

        // ---- O += P V ----
#pragma unroll
        for (int kk = 0; kk < 4; kk++) {
            uint32_t ap[4] = {ph[2 * kk][0], ph[2 * kk][1],
                              ph[2 * kk + 1][0], ph[2 * kk + 1][1]};
            uint32_t bv[8][2];
#pragma unroll
            for (int jb = 0; jb < 4; jb++) {
                int row = kk * 16 + (lane & 7) + ((lane >> 3) & 1) * 8;
                int col = jb * 16 + ((lane >= 16) ? 8 : 0);
                uint32_t r0, r1, r2, r3;
                ldmatrix_x4_trans(r0, r1, r2, r3, smem_u32(&tV[row * 72 + col]));
                bv[jb * 2][0] = r0; bv[jb * 2][1] = r1;
                bv[jb * 2 + 1][0] = r2; bv[jb * 2 + 1][1] = r3;
            }
#pragma unroll
            for (int j = 0; j < 8; j++) mma16816(o[j], ap, bv[j]);
        }
        __syncthreads();  // protect buf `cur` before it is re-filled at it+1
    }

    // ---- epilogue: normalize, write fp32 [b, s, h*64+d] ----
    float inv0 = 1.f / lrow[0], inv1 = 1.f / lrow[1];
#pragma unroll
    for (int j = 0; j < 8; j++) {
        int row0 = q0 + wr0 + g;
        int col = j * 8 + t4 * 2;
        size_t base0 = ((size_t)(b * SEQ + row0)) * HID + h * 64 + col;
        size_t base1 = ((size_t)(b * SEQ + row0 + 8)) * HID + h * 64 + col;
        float2 v0 = make_float2(o[j][0] * inv0, o[j][1] * inv0);
        float2 v1 = make_float2(o[j][2] * inv1, o[j][3] * inv1);
        *(float2*)&out[base0] = v0;
        *(float2*)&out[base1] = v1;
    }
}

// ---------------------------------------------------------------------------
extern "C" void kernel_launch(void* const* d_in, const int* in_sizes, int n_in,
                              void* d_out, int out_size) {
    const float* former = (const float*)d_in[0];
    const float* latter = (const float*)d_in[1];
    const float* mask   = (const float*)d_in[2];
    const float* Wq = (const float*)d_in[3];
    const float* bq = (const float*)d_in[4];
    const float* Wk = (const float*)d_in[5];
    const float* bk = (const float*)d_in[6];
    const float* Wv = (const float*)d_in[7];
    const float* bv = (const float*)d_in[8];

    size_t cvt_blocks = (CVT_TOTAL / 4 + 255) / 256;
    convert_inputs<<<(unsigned)cvt_blocks, 256>>>(former, latter, Wq, Wk, Wv);

    dim3 g1(HID / 128, (NB * SEQ) / 128, 3);
    qkv_gemm<<<g1, 256>>>(bq, bk, bv);

    dim3 g2(SEQ / 64, NB * NH);
    flash_attn<<<g2, 128>>>(mask, (float*)d_out);
}